// round 13
// baseline (speedup 1.0000x reference)
#include <cuda_runtime.h>

#define NROWS 32768
#define DIM   128
#define NC    512
#define TOPK  10
#define MTILE 32
#define NTHR  256
#define NCAND 16

typedef unsigned long long u64;

// smem layout (bytes)
#define BSTRIDE 36                      // B tf32 tile row stride (floats)
#define XSTRIDE 132                     // x f32 stage row stride (floats)
#define SSTRIDE 520                     // approx score row stride (floats)
#define OFF_B    0                      // [512][36] u32 = 73728 ; approx score overlay [32][520] f32 = 66560
#define OFF_XS   73728                  // [32][132] f32 = 16896
#define OFF_X2S  (OFF_XS + 16896)       // [32] f32 (pad 128)
#define OFF_LT   (OFF_X2S + 128)        // [32][4][16] u64 = 16384
#define OFF_CAND (OFF_LT + 16384)       // [32][16] i32 = 2048
#define OFF_EX   (OFF_CAND + 2048)      // [32][16] u64 = 4096
#define OFF_FIDX (OFF_EX + 4096)        // [32][10] i32 = 1280
#define SMEM_TOTAL (OFF_FIDX + 1280)    // 114560 -> 2 CTAs/SM

__device__ float    g_c2[NC];
__device__ unsigned g_cc_tf32[NC * DIM];

// XLA GPU row-reduction for sum(v*v) — empirically bit-exact vs reference. DO NOT CHANGE.
__device__ __forceinline__ float xla_row_sumsq(const float* __restrict__ row, int lane) {
    float4 v = *reinterpret_cast<const float4*>(row + 4 * lane);
    float p = __fmul_rn(v.x, v.x);
    p = __fadd_rn(p, __fmul_rn(v.y, v.y));
    p = __fadd_rn(p, __fmul_rn(v.z, v.z));
    p = __fadd_rn(p, __fmul_rn(v.w, v.w));
#pragma unroll
    for (int off = 16; off > 0; off >>= 1)
        p = __fadd_rn(p, __shfl_down_sync(0xffffffffu, p, off));
    return __shfl_sync(0xffffffffu, p, 0);
}

__device__ __forceinline__ unsigned to_tf32(float f) {
    unsigned o;
    asm("cvt.rna.tf32.f32 %0, %1;" : "=r"(o) : "f"(f));
    return o;
}

// exact c2 + tf32 conversion of centers
__global__ void c2_kernel(const float* __restrict__ cc) {
    int warp = threadIdx.x >> 5;
    int lane = threadIdx.x & 31;
    int c = blockIdx.x * 8 + warp;
    float s = xla_row_sumsq(cc + (size_t)c * DIM, lane);
    if (lane == 0) g_c2[c] = s;
#pragma unroll
    for (int j = 0; j < 4; ++j) {
        int k = lane + 32 * j;
        g_cc_tf32[c * DIM + k] = to_tf32(cc[(size_t)c * DIM + k]);
    }
}

__device__ __forceinline__ void mma_tf32(float& d0, float& d1, float& d2, float& d3,
                                         unsigned a0, unsigned a1, unsigned a2, unsigned a3,
                                         unsigned b0, unsigned b1) {
    asm("mma.sync.aligned.m16n8k8.row.col.f32.tf32.tf32.f32 "
        "{%0,%1,%2,%3}, {%4,%5,%6,%7}, {%8,%9}, {%0,%1,%2,%3};"
        : "+f"(d0), "+f"(d1), "+f"(d2), "+f"(d3)
        : "r"(a0), "r"(a1), "r"(a2), "r"(a3), "r"(b0), "r"(b1));
}

// monotone float->u32 (handles negatives) for approx-score keys
__device__ __forceinline__ unsigned ford(float f) {
    unsigned u = __float_as_uint(f);
    return (u & 0x80000000u) ? ~u : (u | 0x80000000u);
}

__global__ __launch_bounds__(NTHR, 2)
void kmeans_topk_kernel(const float* __restrict__ x,
                        const float* __restrict__ cc,
                        float* __restrict__ out) {
    extern __shared__ char smraw[];
    unsigned* Bs   = reinterpret_cast<unsigned*>(smraw + OFF_B);   // [512][36] tf32
    float*    score= reinterpret_cast<float*>(smraw + OFF_B);      // overlay [32][520]
    float*    xs   = reinterpret_cast<float*>(smraw + OFF_XS);     // [32][132] exact f32
    float*    x2s  = reinterpret_cast<float*>(smraw + OFF_X2S);    // [32]
    u64*      LT   = reinterpret_cast<u64*>(smraw + OFF_LT);       // [32][4][16]
    int*      CAND = reinterpret_cast<int*>(smraw + OFF_CAND);     // [32][16]
    u64*      EX   = reinterpret_cast<u64*>(smraw + OFF_EX);       // [32][16]
    int*      fidx = reinterpret_cast<int*>(smraw + OFF_FIDX);     // [32][10]

    const int tx   = threadIdx.x;
    const int row0 = blockIdx.x * MTILE;
    const int lane = tx & 31;
    const int warp = tx >> 5;     // 0..7
    const int mh   = warp & 1;    // row half: rows mh*16..mh*16+15
    const int nq   = warp >> 1;   // center quarter: nq*128..nq*128+127
    const int g    = lane >> 2;   // 0..7
    const int t    = lane & 3;    // 0..3
    const int rb   = mh * 16;

    // ---- stage exact x tile [32][128] into smem ----
    {
        const float4* x4 = reinterpret_cast<const float4*>(x) + (size_t)row0 * 32;
#pragma unroll
        for (int j = 0; j < 4; ++j) {
            int i = tx + 256 * j;          // 0..1023
            int r = i >> 5, kq = i & 31;
            *reinterpret_cast<float4*>(xs + r * XSTRIDE + kq * 4) = x4[i];
        }
    }

    // ---- x2[row] exact XLA order; warp w does rows w, w+8, w+16, w+24 ----
#pragma unroll
    for (int j = 0; j < 4; ++j) {
        int rl = warp + 8 * j;
        float s = xla_row_sumsq(x + (size_t)(row0 + rl) * DIM, lane);
        if (lane == 0) x2s[rl] = s;
    }

    // ---- tf32 filter GEMM: approx[32][512] = X*C^T via m16n8k8 ----
    float acc[16][4];
#pragma unroll
    for (int nt = 0; nt < 16; ++nt)
#pragma unroll
        for (int j = 0; j < 4; ++j) acc[nt][j] = 0.0f;

    for (int ktc = 0; ktc < 4; ++ktc) {
        const int kt = ktc * 32;
        __syncthreads();
        // load B tf32 tile [512][32] -> Bs[c][k] (pad 36)
#pragma unroll
        for (int j = 0; j < 16; ++j) {
            int i = tx + 256 * j;          // 0..4095
            int c = i >> 3, kq = i & 7;
            uint4 v = *reinterpret_cast<const uint4*>(g_cc_tf32 + c * DIM + kt + kq * 4);
            *reinterpret_cast<uint4*>(Bs + c * BSTRIDE + kq * 4) = v;
        }
        __syncthreads();

#pragma unroll
        for (int s = 0; s < 4; ++s) {
            const int k0 = s * 8;
            // A fragment (shared across the 16 n-tiles): conflict-free LDS + cvt
            unsigned a0 = to_tf32(xs[(rb + g) * XSTRIDE + kt + k0 + t]);
            unsigned a1 = to_tf32(xs[(rb + g + 8) * XSTRIDE + kt + k0 + t]);
            unsigned a2 = to_tf32(xs[(rb + g) * XSTRIDE + kt + k0 + t + 4]);
            unsigned a3 = to_tf32(xs[(rb + g + 8) * XSTRIDE + kt + k0 + t + 4]);
#pragma unroll
            for (int nt = 0; nt < 16; ++nt) {
                const unsigned* bp = Bs + (nq * 128 + nt * 8 + g) * BSTRIDE + k0 + t;
                unsigned b0 = bp[0];
                unsigned b1 = bp[4];
                mma_tf32(acc[nt][0], acc[nt][1], acc[nt][2], acc[nt][3],
                         a0, a1, a2, a3, b0, b1);
            }
        }
    }
    __syncthreads();   // all warps done reading Bs before score overlay

    // approx score = c2[c] - 2*dot (monotone proxy; filter only)
#pragma unroll
    for (int nt = 0; nt < 16; ++nt) {
        int c0 = nq * 128 + nt * 8 + 2 * t;
        float c2lo = __ldg(&g_c2[c0]), c2hi = __ldg(&g_c2[c0 + 1]);
        float2 s0 = make_float2(c2lo - 2.0f * acc[nt][0], c2hi - 2.0f * acc[nt][1]);
        float2 s1 = make_float2(c2lo - 2.0f * acc[nt][2], c2hi - 2.0f * acc[nt][3]);
        *reinterpret_cast<float2*>(score + (rb + g) * SSTRIDE + c0) = s0;
        *reinterpret_cast<float2*>(score + (rb + g + 8) * SSTRIDE + c0) = s1;
    }
    __syncthreads();

    // ---- filter: per row approx top-16 (4 threads/row, 128 vals each) ----
    if (tx < 128) {
        const int tsub = tx & 3;
        const int rl = tx >> 2;
        const int base = tsub * 128;
        const int rot = (tx * 5) & 127;   // bank spread; order-safe (u64 keys)
        u64 bs[NCAND];
#pragma unroll
        for (int p = 0; p < NCAND; ++p) bs[p] = ~0ull;
        for (int v = 0; v < 128; ++v) {
            int c = base + ((v + rot) & 127);
            u64 key = ((u64)ford(score[rl * SSTRIDE + c]) << 32) | (unsigned)c;
            if (key < bs[NCAND - 1]) {
                bs[NCAND - 1] = key;
#pragma unroll
                for (int p = NCAND - 1; p > 0; --p)
                    if (bs[p] < bs[p - 1]) { u64 tm = bs[p]; bs[p] = bs[p - 1]; bs[p - 1] = tm; }
            }
        }
#pragma unroll
        for (int p = 0; p < NCAND; ++p) LT[(rl * 4 + tsub) * NCAND + p] = bs[p];
    }
    __syncthreads();

    // ---- merge 64 -> 16 candidates per row ----
    if (tx < MTILE) {
        const int rl = tx;
        u64 bs[NCAND];
#pragma unroll
        for (int p = 0; p < NCAND; ++p) bs[p] = ~0ull;
        for (int v = 0; v < 4 * NCAND; ++v) {
            u64 key = LT[rl * 4 * NCAND + v];
            if (key < bs[NCAND - 1]) {
                bs[NCAND - 1] = key;
#pragma unroll
                for (int p = NCAND - 1; p > 0; --p)
                    if (bs[p] < bs[p - 1]) { u64 tm = bs[p]; bs[p] = bs[p - 1]; bs[p - 1] = tm; }
            }
        }
#pragma unroll
        for (int p = 0; p < NCAND; ++p) CAND[rl * NCAND + p] = (int)(unsigned)(bs[p] & 0xffffffffu);
    }
    __syncthreads();

    // ---- exact rescore of 16 candidates/row (bit-exact reference chain) ----
    {
        const int rl = tx >> 3;
        const int tsub = tx & 7;
        const float x2v = x2s[rl];
#pragma unroll
        for (int jj = 0; jj < 2; ++jj) {
            int slot = tsub + 8 * jj;
            int c = CAND[rl * NCAND + slot];
            const float4* cp = reinterpret_cast<const float4*>(cc + (size_t)c * DIM);
            const float* xp = xs + rl * XSTRIDE;
            float s = 0.0f;
            // sequential ascending-k FMA chain (matches cublas per-element order)
#pragma unroll 8
            for (int q = 0; q < 32; ++q) {
                float4 cv = __ldg(cp + q);
                s = __fmaf_rn(xp[4 * q + 0], cv.x, s);
                s = __fmaf_rn(xp[4 * q + 1], cv.y, s);
                s = __fmaf_rn(xp[4 * q + 2], cv.z, s);
                s = __fmaf_rn(xp[4 * q + 3], cv.w, s);
            }
            float u = __fadd_rn(__fsub_rn(x2v, 2.0f * s), g_c2[c]);
            float d = __fsqrt_rn(fmaxf(u, 0.0f));
            EX[rl * NCAND + slot] = ((u64)__float_as_uint(d) << 32) | (unsigned)c;
        }
    }
    __syncthreads();

    // ---- exact keyed top-10 of 16 per row ----
    if (tx < MTILE) {
        const int rl = tx;
        u64 bs[TOPK];
#pragma unroll
        for (int p = 0; p < TOPK; ++p) bs[p] = ~0ull;
#pragma unroll
        for (int v = 0; v < NCAND; ++v) {
            u64 key = EX[rl * NCAND + v];
            if (key < bs[TOPK - 1]) {
                bs[TOPK - 1] = key;
#pragma unroll
                for (int p = TOPK - 1; p > 0; --p)
                    if (bs[p] < bs[p - 1]) { u64 tm = bs[p]; bs[p] = bs[p - 1]; bs[p - 1] = tm; }
            }
        }
#pragma unroll
        for (int p = 0; p < TOPK; ++p) fidx[rl * TOPK + p] = (int)(unsigned)(bs[p] & 0xffffffffu);
    }
    __syncthreads();

    // ---- gather epilogue: out[row*10+t] = x[idx] (idx < 512 -> L2-hot) ----
    {
        const float4* x4 = reinterpret_cast<const float4*>(x);
        float4* out4 = reinterpret_cast<float4*>(out);
#pragma unroll
        for (int it = 0; it < 40; ++it) {
            int i = tx + NTHR * it;         // 0 .. 10239
            int orow = i >> 5;              // 0 .. 319
            int e = i & 31;
            int rl = orow / 10;
            int tt = orow - rl * 10;
            int idx = fidx[rl * TOPK + tt];
            size_t src = (size_t)idx * 32 + e;
            size_t dst = ((size_t)(row0 + rl) * 10 + tt) * 32 + e;
            out4[dst] = __ldg(&x4[src]);
        }
    }
}

extern "C" void kernel_launch(void* const* d_in, const int* in_sizes, int n_in,
                              void* d_out, int out_size) {
    const float* x  = (const float*)d_in[0];
    const float* cc = (const float*)d_in[1];
    float* out = (float*)d_out;

    cudaFuncSetAttribute(kmeans_topk_kernel,
                         cudaFuncAttributeMaxDynamicSharedMemorySize, SMEM_TOTAL);
    c2_kernel<<<NC / 8, 256>>>(cc);
    kmeans_topk_kernel<<<NROWS / MTILE, NTHR, SMEM_TOTAL>>>(x, cc, out);
}

// round 14
// speedup vs baseline: 1.4347x; 1.4347x over previous
#include <cuda_runtime.h>

#define NROWS 32768
#define DIM   128
#define NC    512
#define TOPK  10
#define MTILE 32
#define NTHR  512
#define NCAND 16
#define KSTRIDE 517                     // keys row stride (u32) — 5 mod 32

typedef unsigned long long u64;
typedef unsigned u32;

// smem layout (bytes)
#define XSTRIDE 132
#define OFF_B    0                      // Bs [512][36] u32 = 73728 ; keys overlay [32][517] u32 = 66176
#define OFF_XS   73728                  // [32][132] f32 = 16896
#define OFF_X2S  90624                  // [32] f32 (+pad) = 128
#define OFF_ML   90752                  // [32][4][16] u32 = 8192
#define OFF_CAND 98944                  // [32][16] i32 = 2048
#define OFF_EX   100992                 // [32][16] u64 = 4096
#define OFF_FIDX 105088                 // [32][10] i32 = 1280
#define SMEM_TOTAL 106368               // x2 = 207.8KB -> 2 CTAs/SM

__device__ float g_c2[NC];
__device__ u32   g_cc_tf32[NC * DIM];

// XLA GPU row-reduction for sum(v*v) — empirically bit-exact vs reference. DO NOT CHANGE.
__device__ __forceinline__ float xla_row_sumsq(const float* __restrict__ row, int lane) {
    float4 v = *reinterpret_cast<const float4*>(row + 4 * lane);
    float p = __fmul_rn(v.x, v.x);
    p = __fadd_rn(p, __fmul_rn(v.y, v.y));
    p = __fadd_rn(p, __fmul_rn(v.z, v.z));
    p = __fadd_rn(p, __fmul_rn(v.w, v.w));
#pragma unroll
    for (int off = 16; off > 0; off >>= 1)
        p = __fadd_rn(p, __shfl_down_sync(0xffffffffu, p, off));
    return __shfl_sync(0xffffffffu, p, 0);
}

__device__ __forceinline__ u32 to_tf32(float f) {
    u32 o;
    asm("cvt.rna.tf32.f32 %0, %1;" : "=r"(o) : "f"(f));
    return o;
}

__global__ void c2_kernel(const float* __restrict__ cc) {
    int warp = threadIdx.x >> 5;
    int lane = threadIdx.x & 31;
    int c = blockIdx.x * 8 + warp;
    float s = xla_row_sumsq(cc + (size_t)c * DIM, lane);
    if (lane == 0) g_c2[c] = s;
#pragma unroll
    for (int j = 0; j < 4; ++j) {
        int k = lane + 32 * j;
        g_cc_tf32[c * DIM + k] = to_tf32(cc[(size_t)c * DIM + k]);
    }
}

__device__ __forceinline__ void mma_tf32(float& d0, float& d1, float& d2, float& d3,
                                         u32 a0, u32 a1, u32 a2, u32 a3,
                                         u32 b0, u32 b1) {
    asm("mma.sync.aligned.m16n8k8.row.col.f32.tf32.tf32.f32 "
        "{%0,%1,%2,%3}, {%4,%5,%6,%7}, {%8,%9}, {%0,%1,%2,%3};"
        : "+f"(d0), "+f"(d1), "+f"(d2), "+f"(d3)
        : "r"(a0), "r"(a1), "r"(a2), "r"(a3), "r"(b0), "r"(b1));
}

__device__ __forceinline__ u32 ford(float f) {
    u32 u = __float_as_uint(f);
    return (u & 0x80000000u) ? ~u : (u | 0x80000000u);
}

__global__ __launch_bounds__(NTHR, 2)
void kmeans_topk_kernel(const float* __restrict__ x,
                        const float* __restrict__ cc,
                        float* __restrict__ out) {
    extern __shared__ char smraw[];
    u32*   Bs   = reinterpret_cast<u32*>(smraw + OFF_B);     // [512][36]
    u32*   keys = reinterpret_cast<u32*>(smraw + OFF_B);     // overlay [32][517]
    float* xs   = reinterpret_cast<float*>(smraw + OFF_XS);  // [32][132]
    float* x2s  = reinterpret_cast<float*>(smraw + OFF_X2S); // [32]
    u32*   ML   = reinterpret_cast<u32*>(smraw + OFF_ML);    // [32][4][16]
    int*   CAND = reinterpret_cast<int*>(smraw + OFF_CAND);  // [32][16]
    u64*   EX   = reinterpret_cast<u64*>(smraw + OFF_EX);    // [32][16]
    int*   fidx = reinterpret_cast<int*>(smraw + OFF_FIDX);  // [32][10]

    const int tx   = threadIdx.x;
    const int row0 = blockIdx.x * MTILE;
    const int lane = tx & 31;
    const int warp = tx >> 5;     // 0..15
    const int mh   = warp & 1;    // row half
    const int nq   = warp >> 1;   // center eighth (64 centers)
    const int g    = lane >> 2;   // 0..7
    const int t    = lane & 3;    // 0..3
    const int rb   = mh * 16;

    // ---- stage exact x tile [32][128] ----
    {
        const float4* x4 = reinterpret_cast<const float4*>(x) + (size_t)row0 * 32;
#pragma unroll
        for (int j = 0; j < 2; ++j) {
            int i = tx + NTHR * j;         // 0..1023
            int r = i >> 5, kq = i & 31;
            *reinterpret_cast<float4*>(xs + r * XSTRIDE + kq * 4) = x4[i];
        }
    }
    // ---- x2[row] exact XLA order; warp w does rows w and w+16 ----
#pragma unroll
    for (int j = 0; j < 2; ++j) {
        int rl = warp + 16 * j;
        float s = xla_row_sumsq(x + (size_t)(row0 + rl) * DIM, lane);
        if (lane == 0) x2s[rl] = s;
    }

    // ---- tf32 filter GEMM: per warp 16 rows x 64 centers ----
    float acc[8][4];
#pragma unroll
    for (int nt = 0; nt < 8; ++nt)
#pragma unroll
        for (int j = 0; j < 4; ++j) acc[nt][j] = 0.0f;

    for (int ktc = 0; ktc < 4; ++ktc) {
        const int kt = ktc * 32;
        __syncthreads();
#pragma unroll
        for (int j = 0; j < 8; ++j) {
            int i = tx + NTHR * j;         // 0..4095
            int c = i >> 3, kq = i & 7;
            uint4 v = *reinterpret_cast<const uint4*>(g_cc_tf32 + c * DIM + kt + kq * 4);
            *reinterpret_cast<uint4*>(Bs + c * 36 + kq * 4) = v;
        }
        __syncthreads();
#pragma unroll
        for (int s = 0; s < 4; ++s) {
            const int k0 = kt + s * 8;
            u32 a0 = to_tf32(xs[(rb + g) * XSTRIDE + k0 + t]);
            u32 a1 = to_tf32(xs[(rb + g + 8) * XSTRIDE + k0 + t]);
            u32 a2 = to_tf32(xs[(rb + g) * XSTRIDE + k0 + t + 4]);
            u32 a3 = to_tf32(xs[(rb + g + 8) * XSTRIDE + k0 + t + 4]);
#pragma unroll
            for (int nt = 0; nt < 8; ++nt) {
                const u32* bp = Bs + (nq * 64 + nt * 8 + g) * 36 + s * 8 + t;
                mma_tf32(acc[nt][0], acc[nt][1], acc[nt][2], acc[nt][3],
                         a0, a1, a2, a3, bp[0], bp[4]);
            }
        }
    }
    __syncthreads();

    // ---- epilogue: u32 keys = (ford(c2 - 2*dot) & ~511) | c (approx; filter only) ----
#pragma unroll
    for (int nt = 0; nt < 8; ++nt) {
        int c0 = nq * 64 + nt * 8 + 2 * t;
        float c2lo = __ldg(&g_c2[c0]), c2hi = __ldg(&g_c2[c0 + 1]);
        int ra = (rb + g) * KSTRIDE, rbx = (rb + g + 8) * KSTRIDE;
        keys[ra + c0]      = (ford(c2lo - 2.0f * acc[nt][0]) & ~511u) | (u32)c0;
        keys[ra + c0 + 1]  = (ford(c2hi - 2.0f * acc[nt][1]) & ~511u) | (u32)(c0 + 1);
        keys[rbx + c0]     = (ford(c2lo - 2.0f * acc[nt][2]) & ~511u) | (u32)c0;
        keys[rbx + c0 + 1] = (ford(c2hi - 2.0f * acc[nt][3]) & ~511u) | (u32)(c0 + 1);
    }
    __syncthreads();

    // ---- filter: 16 threads/row, each top-16 of its 32 keys; write back sorted ----
    {
        const int rl = tx >> 4;
        const int j = tx & 15;
        const int base = rl * KSTRIDE + 32 * j;
        const int rot = (j + 13 * (rl & 1)) & 31;
        u32 bs[NCAND];
#pragma unroll
        for (int p = 0; p < NCAND; ++p) bs[p] = 0xFFFFFFFFu;
        for (int v = 0; v < 32; ++v) {
            u32 k = keys[base + ((v + rot) & 31)];
            if (k < bs[NCAND - 1]) {
                bs[NCAND - 1] = k;
#pragma unroll
                for (int p = NCAND - 1; p > 0; --p)
                    if (bs[p] < bs[p - 1]) { u32 tm = bs[p]; bs[p] = bs[p - 1]; bs[p - 1] = tm; }
            }
        }
#pragma unroll
        for (int p = 0; p < NCAND; ++p) keys[base + p] = bs[p];  // own segment only
    }
    __syncthreads();

    // ---- merge stage 1: 4 threads/row, 4-way sorted merge of 4 lists -> top-16 ----
    if (tx < 128) {
        const int rl = tx >> 2;
        const int q = tx & 3;
        const u32* L = keys + rl * KSTRIDE + 32 * (4 * q);
        int p0 = 0, p1 = 0, p2 = 0, p3 = 0;
        u32 h0 = L[0], h1 = L[32], h2 = L[64], h3 = L[96];
        u32* outp = ML + rl * 64 + q * 16;
#pragma unroll
        for (int m = 0; m < NCAND; ++m) {
            u32 mn = h0; int a = 0;
            if (h1 < mn) { mn = h1; a = 1; }
            if (h2 < mn) { mn = h2; a = 2; }
            if (h3 < mn) { mn = h3; a = 3; }
            outp[m] = mn;
            if (a == 0)      { ++p0; h0 = (p0 < 16) ? L[p0]      : 0xFFFFFFFFu; }
            else if (a == 1) { ++p1; h1 = (p1 < 16) ? L[32 + p1] : 0xFFFFFFFFu; }
            else if (a == 2) { ++p2; h2 = (p2 < 16) ? L[64 + p2] : 0xFFFFFFFFu; }
            else             { ++p3; h3 = (p3 < 16) ? L[96 + p3] : 0xFFFFFFFFu; }
        }
    }
    __syncthreads();

    // ---- merge stage 2: 1 thread/row, 4-way merge -> 16 candidate centers ----
    if (tx < MTILE) {
        const int rl = tx;
        const u32* L = ML + rl * 64;
        int p0 = 0, p1 = 0, p2 = 0, p3 = 0;
        u32 h0 = L[0], h1 = L[16], h2 = L[32], h3 = L[48];
#pragma unroll
        for (int m = 0; m < NCAND; ++m) {
            u32 mn = h0; int a = 0;
            if (h1 < mn) { mn = h1; a = 1; }
            if (h2 < mn) { mn = h2; a = 2; }
            if (h3 < mn) { mn = h3; a = 3; }
            CAND[rl * NCAND + m] = (int)(mn & 511u);
            if (a == 0)      { ++p0; h0 = (p0 < 16) ? L[p0]      : 0xFFFFFFFFu; }
            else if (a == 1) { ++p1; h1 = (p1 < 16) ? L[16 + p1] : 0xFFFFFFFFu; }
            else if (a == 2) { ++p2; h2 = (p2 < 16) ? L[32 + p2] : 0xFFFFFFFFu; }
            else             { ++p3; h3 = (p3 < 16) ? L[48 + p3] : 0xFFFFFFFFu; }
        }
    }
    __syncthreads();

    // ---- exact rescore: 1 thread per (row, candidate) — bit-exact reference chain ----
    {
        const int rl = tx >> 4;
        const int sidx = tx & 15;
        const int c = CAND[rl * NCAND + sidx];
        const float4* cp = reinterpret_cast<const float4*>(cc + (size_t)c * DIM);
        const float* xp = xs + rl * XSTRIDE;
        float s = 0.0f;
        // sequential ascending-k FMA chain (matches cublas per-element order)
#pragma unroll 8
        for (int q = 0; q < 32; ++q) {
            float4 cv = __ldg(cp + q);
            s = __fmaf_rn(xp[4 * q + 0], cv.x, s);
            s = __fmaf_rn(xp[4 * q + 1], cv.y, s);
            s = __fmaf_rn(xp[4 * q + 2], cv.z, s);
            s = __fmaf_rn(xp[4 * q + 3], cv.w, s);
        }
        float u = __fadd_rn(__fsub_rn(x2s[rl], 2.0f * s), __ldg(&g_c2[c]));
        float d = __fsqrt_rn(fmaxf(u, 0.0f));
        EX[rl * NCAND + sidx] = ((u64)__float_as_uint(d) << 32) | (u32)c;
    }
    __syncthreads();

    // ---- exact keyed top-10 of 16 per row ----
    if (tx < MTILE) {
        const int rl = tx;
        u64 bs[TOPK];
#pragma unroll
        for (int p = 0; p < TOPK; ++p) bs[p] = ~0ull;
#pragma unroll
        for (int v = 0; v < NCAND; ++v) {
            u64 key = EX[rl * NCAND + v];
            if (key < bs[TOPK - 1]) {
                bs[TOPK - 1] = key;
#pragma unroll
                for (int p = TOPK - 1; p > 0; --p)
                    if (bs[p] < bs[p - 1]) { u64 tm = bs[p]; bs[p] = bs[p - 1]; bs[p - 1] = tm; }
            }
        }
#pragma unroll
        for (int p = 0; p < TOPK; ++p) fidx[rl * TOPK + p] = (int)(u32)(bs[p] & 0xffffffffu);
    }
    __syncthreads();

    // ---- gather epilogue: out[row*10+t] = x[idx] (idx < 512 -> L2-hot) ----
    {
        const float4* x4 = reinterpret_cast<const float4*>(x);
        float4* out4 = reinterpret_cast<float4*>(out);
#pragma unroll
        for (int it = 0; it < 20; ++it) {
            int i = tx + NTHR * it;         // 0 .. 10239
            int orow = i >> 5;              // 0 .. 319
            int e = i & 31;
            int rl = orow / 10;
            int tt = orow - rl * 10;
            int idx = fidx[rl * TOPK + tt];
            size_t src = (size_t)idx * 32 + e;
            size_t dst = ((size_t)(row0 + rl) * 10 + tt) * 32 + e;
            out4[dst] = __ldg(&x4[src]);
        }
    }
}

extern "C" void kernel_launch(void* const* d_in, const int* in_sizes, int n_in,
                              void* d_out, int out_size) {
    const float* x  = (const float*)d_in[0];
    const float* cc = (const float*)d_in[1];
    float* out = (float*)d_out;

    cudaFuncSetAttribute(kmeans_topk_kernel,
                         cudaFuncAttributeMaxDynamicSharedMemorySize, SMEM_TOTAL);
    c2_kernel<<<NC / 8, 256>>>(cc);
    kmeans_topk_kernel<<<NROWS / MTILE, NTHR, SMEM_TOTAL>>>(x, cc, out);
}

// round 15
// speedup vs baseline: 1.5394x; 1.0730x over previous
#include <cuda_runtime.h>

#define NROWS 32768
#define DIM   128
#define NC    512
#define TOPK  10
#define MTILE 32
#define NTHR  512
#define NCAND 16
#define KSTRIDE 518                    // keys row stride (u32), even + 6 mod 32

typedef unsigned long long u64;
typedef unsigned u32;

// smem layout (bytes)
#define XSTRIDE 132
#define BSTR    20                      // Bs row stride (u32; 16 data + 4 pad)
#define OFF_K    0                      // keys [32][518] u32 = 66304 ; Bs [512][20] overlays (40960)
#define OFF_XS   66304                  // [32][132] f32 = 16896
#define OFF_X2S  83200                  // [32] f32 (+pad) = 128
#define OFF_ML   83328                  // [32][4][16] u32 = 8192
#define OFF_CAND 91520                  // [32][16] i32 = 2048
#define OFF_EX   93568                  // [32][16] u64 = 4096
#define SMEM_TOTAL 97664                // x2 = 190.8KB -> 2 CTAs/SM

__device__ float g_c2[NC];
__device__ u32   g_cc_bf16[NC * DIM / 2];    // [c][k/2] packed bf16x2
__device__ int   g_fidx[NROWS * TOPK];

// XLA GPU row-reduction for sum(v*v) — empirically bit-exact vs reference. DO NOT CHANGE.
__device__ __forceinline__ float xla_row_sumsq(const float* __restrict__ row, int lane) {
    float4 v = *reinterpret_cast<const float4*>(row + 4 * lane);
    float p = __fmul_rn(v.x, v.x);
    p = __fadd_rn(p, __fmul_rn(v.y, v.y));
    p = __fadd_rn(p, __fmul_rn(v.z, v.z));
    p = __fadd_rn(p, __fmul_rn(v.w, v.w));
#pragma unroll
    for (int off = 16; off > 0; off >>= 1)
        p = __fadd_rn(p, __shfl_down_sync(0xffffffffu, p, off));
    return __shfl_sync(0xffffffffu, p, 0);
}

__device__ __forceinline__ u32 pack_bf16(float lo, float hi) {
    u32 o;
    asm("cvt.rn.bf16x2.f32 %0, %1, %2;" : "=r"(o) : "f"(hi), "f"(lo));
    return o;
}

__global__ void c2_kernel(const float* __restrict__ cc) {
    int warp = threadIdx.x >> 5;
    int lane = threadIdx.x & 31;
    int c = blockIdx.x * 8 + warp;
    float s = xla_row_sumsq(cc + (size_t)c * DIM, lane);
    if (lane == 0) g_c2[c] = s;
#pragma unroll
    for (int j = 0; j < 2; ++j) {
        int k2 = lane + 32 * j;
        g_cc_bf16[c * 64 + k2] = pack_bf16(cc[(size_t)c * DIM + 2 * k2],
                                           cc[(size_t)c * DIM + 2 * k2 + 1]);
    }
}

__device__ __forceinline__ void mma_bf16(float& d0, float& d1, float& d2, float& d3,
                                         u32 a0, u32 a1, u32 a2, u32 a3,
                                         u32 b0, u32 b1) {
    asm("mma.sync.aligned.m16n8k16.row.col.f32.bf16.bf16.f32 "
        "{%0,%1,%2,%3}, {%4,%5,%6,%7}, {%8,%9}, {%0,%1,%2,%3};"
        : "+f"(d0), "+f"(d1), "+f"(d2), "+f"(d3)
        : "r"(a0), "r"(a1), "r"(a2), "r"(a3), "r"(b0), "r"(b1));
}

__device__ __forceinline__ u32 ford(float f) {
    u32 u = __float_as_uint(f);
    return (u & 0x80000000u) ? ~u : (u | 0x80000000u);
}

__global__ __launch_bounds__(NTHR, 2)
void kmeans_topk_kernel(const float* __restrict__ x,
                        const float* __restrict__ cc) {
    extern __shared__ char smraw[];
    u32*   Bs   = reinterpret_cast<u32*>(smraw + OFF_K);     // [512][20]
    u32*   keys = reinterpret_cast<u32*>(smraw + OFF_K);     // overlay [32][518]
    float* xs   = reinterpret_cast<float*>(smraw + OFF_XS);  // [32][132]
    float* x2s  = reinterpret_cast<float*>(smraw + OFF_X2S); // [32]
    u32*   ML   = reinterpret_cast<u32*>(smraw + OFF_ML);    // [32][4][16]
    int*   CAND = reinterpret_cast<int*>(smraw + OFF_CAND);  // [32][16]
    u64*   EX   = reinterpret_cast<u64*>(smraw + OFF_EX);    // [32][16]

    const int tx   = threadIdx.x;
    const int row0 = blockIdx.x * MTILE;
    const int lane = tx & 31;
    const int warp = tx >> 5;     // 0..15
    const int mh   = warp & 1;
    const int nq   = warp >> 1;   // 0..7, 64 centers each
    const int g    = lane >> 2;   // 0..7
    const int t    = lane & 3;    // 0..3
    const int rb   = mh * 16;

    // ---- stage exact x tile [32][128] ----
    {
        const float4* x4 = reinterpret_cast<const float4*>(x) + (size_t)row0 * 32;
#pragma unroll
        for (int j = 0; j < 2; ++j) {
            int i = tx + NTHR * j;
            int r = i >> 5, kq = i & 31;
            *reinterpret_cast<float4*>(xs + r * XSTRIDE + kq * 4) = x4[i];
        }
    }
    // ---- x2[row] exact XLA order ----
#pragma unroll
    for (int j = 0; j < 2; ++j) {
        int rl = warp + 16 * j;
        float s = xla_row_sumsq(x + (size_t)(row0 + rl) * DIM, lane);
        if (lane == 0) x2s[rl] = s;
    }

    // ---- bf16 filter GEMM: per warp 16 rows x 64 centers, m16n8k16 ----
    float acc[8][4];
#pragma unroll
    for (int nt = 0; nt < 8; ++nt)
#pragma unroll
        for (int j = 0; j < 4; ++j) acc[nt][j] = 0.0f;

    for (int ktc = 0; ktc < 4; ++ktc) {
        __syncthreads();
        // B tile: 512 c x 16 u32 (bf16x2) -> Bs stride 20
#pragma unroll
        for (int j = 0; j < 4; ++j) {
            int i = tx + NTHR * j;         // 0..2047
            int c = i >> 2, q = i & 3;
            uint4 v = *reinterpret_cast<const uint4*>(g_cc_bf16 + c * 64 + ktc * 16 + q * 4);
            *reinterpret_cast<uint4*>(Bs + c * BSTR + q * 4) = v;
        }
        __syncthreads();
#pragma unroll
        for (int sp = 0; sp < 2; ++sp) {
            const int k0 = ktc * 32 + sp * 16;
            float2 va = *reinterpret_cast<const float2*>(xs + (rb + g) * XSTRIDE + k0 + 2 * t);
            float2 vb = *reinterpret_cast<const float2*>(xs + (rb + g + 8) * XSTRIDE + k0 + 2 * t);
            float2 vc = *reinterpret_cast<const float2*>(xs + (rb + g) * XSTRIDE + k0 + 8 + 2 * t);
            float2 vd = *reinterpret_cast<const float2*>(xs + (rb + g + 8) * XSTRIDE + k0 + 8 + 2 * t);
            u32 a0 = pack_bf16(va.x, va.y);
            u32 a1 = pack_bf16(vb.x, vb.y);
            u32 a2 = pack_bf16(vc.x, vc.y);
            u32 a3 = pack_bf16(vd.x, vd.y);
#pragma unroll
            for (int nt = 0; nt < 8; ++nt) {
                const u32* bp = Bs + (nq * 64 + nt * 8 + g) * BSTR + sp * 8 + t;
                mma_bf16(acc[nt][0], acc[nt][1], acc[nt][2], acc[nt][3],
                         a0, a1, a2, a3, bp[0], bp[4]);
            }
        }
    }
    __syncthreads();

    // ---- epilogue: u32 keys = (ford(c2 - 2*dot) & ~511) | c ----
#pragma unroll
    for (int nt = 0; nt < 8; ++nt) {
        int c0 = nq * 64 + nt * 8 + 2 * t;
        float c2lo = __ldg(&g_c2[c0]), c2hi = __ldg(&g_c2[c0 + 1]);
        int ra = (rb + g) * KSTRIDE, rbx = (rb + g + 8) * KSTRIDE;
        uint2 ka, kb;
        ka.x = (ford(c2lo - 2.0f * acc[nt][0]) & ~511u) | (u32)c0;
        ka.y = (ford(c2hi - 2.0f * acc[nt][1]) & ~511u) | (u32)(c0 + 1);
        kb.x = (ford(c2lo - 2.0f * acc[nt][2]) & ~511u) | (u32)c0;
        kb.y = (ford(c2hi - 2.0f * acc[nt][3]) & ~511u) | (u32)(c0 + 1);
        *reinterpret_cast<uint2*>(keys + ra + c0) = ka;
        *reinterpret_cast<uint2*>(keys + rbx + c0) = kb;
    }
    __syncthreads();

    // ---- filter: 16 threads/row, top-16 of 32 keys each; write back sorted ----
    {
        const int rl = tx >> 4;
        const int j = tx & 15;
        const int base = rl * KSTRIDE + 32 * j;
        const int rot = (j + 13 * (rl & 1)) & 31;
        u32 bs[NCAND];
#pragma unroll
        for (int p = 0; p < NCAND; ++p) bs[p] = 0xFFFFFFFFu;
        for (int v = 0; v < 32; ++v) {
            u32 k = keys[base + ((v + rot) & 31)];
            if (k < bs[NCAND - 1]) {
                bs[NCAND - 1] = k;
#pragma unroll
                for (int p = NCAND - 1; p > 0; --p)
                    if (bs[p] < bs[p - 1]) { u32 tm = bs[p]; bs[p] = bs[p - 1]; bs[p - 1] = tm; }
            }
        }
#pragma unroll
        for (int p = 0; p < NCAND; ++p) keys[base + p] = bs[p];
    }
    __syncthreads();

    // ---- merge stage 1: 4 threads/row, 4-way sorted merge -> 16 ----
    if (tx < 128) {
        const int rl = tx >> 2;
        const int q = tx & 3;
        const u32* L = keys + rl * KSTRIDE + 32 * (4 * q);
        int p0 = 0, p1 = 0, p2 = 0, p3 = 0;
        u32 h0 = L[0], h1 = L[32], h2 = L[64], h3 = L[96];
        u32* outp = ML + rl * 64 + q * 16;
#pragma unroll
        for (int m = 0; m < NCAND; ++m) {
            u32 mn = h0; int a = 0;
            if (h1 < mn) { mn = h1; a = 1; }
            if (h2 < mn) { mn = h2; a = 2; }
            if (h3 < mn) { mn = h3; a = 3; }
            outp[m] = mn;
            if (a == 0)      { ++p0; h0 = (p0 < 16) ? L[p0]      : 0xFFFFFFFFu; }
            else if (a == 1) { ++p1; h1 = (p1 < 16) ? L[32 + p1] : 0xFFFFFFFFu; }
            else if (a == 2) { ++p2; h2 = (p2 < 16) ? L[64 + p2] : 0xFFFFFFFFu; }
            else             { ++p3; h3 = (p3 < 16) ? L[96 + p3] : 0xFFFFFFFFu; }
        }
    }
    __syncthreads();

    // ---- merge stage 2: 1 thread/row -> 16 candidate centers ----
    if (tx < MTILE) {
        const int rl = tx;
        const u32* L = ML + rl * 64;
        int p0 = 0, p1 = 0, p2 = 0, p3 = 0;
        u32 h0 = L[0], h1 = L[16], h2 = L[32], h3 = L[48];
#pragma unroll
        for (int m = 0; m < NCAND; ++m) {
            u32 mn = h0; int a = 0;
            if (h1 < mn) { mn = h1; a = 1; }
            if (h2 < mn) { mn = h2; a = 2; }
            if (h3 < mn) { mn = h3; a = 3; }
            CAND[rl * NCAND + m] = (int)(mn & 511u);
            if (a == 0)      { ++p0; h0 = (p0 < 16) ? L[p0]      : 0xFFFFFFFFu; }
            else if (a == 1) { ++p1; h1 = (p1 < 16) ? L[16 + p1] : 0xFFFFFFFFu; }
            else if (a == 2) { ++p2; h2 = (p2 < 16) ? L[32 + p2] : 0xFFFFFFFFu; }
            else             { ++p3; h3 = (p3 < 16) ? L[48 + p3] : 0xFFFFFFFFu; }
        }
    }
    __syncthreads();

    // ---- exact rescore: 1 thread per (row, candidate) — bit-exact reference chain ----
    {
        const int rl = tx >> 4;
        const int sidx = tx & 15;
        const int c = CAND[rl * NCAND + sidx];
        const float4* cp = reinterpret_cast<const float4*>(cc + (size_t)c * DIM);
        const float* xp = xs + rl * XSTRIDE;
        float s = 0.0f;
        // sequential ascending-k FMA chain (matches cublas per-element order)
#pragma unroll 8
        for (int q = 0; q < 32; ++q) {
            float4 cv = __ldg(cp + q);
            s = __fmaf_rn(xp[4 * q + 0], cv.x, s);
            s = __fmaf_rn(xp[4 * q + 1], cv.y, s);
            s = __fmaf_rn(xp[4 * q + 2], cv.z, s);
            s = __fmaf_rn(xp[4 * q + 3], cv.w, s);
        }
        float u = __fadd_rn(__fsub_rn(x2s[rl], 2.0f * s), __ldg(&g_c2[c]));
        float d = __fsqrt_rn(fmaxf(u, 0.0f));
        EX[rl * NCAND + sidx] = ((u64)__float_as_uint(d) << 32) | (u32)c;
    }
    __syncthreads();

    // ---- exact keyed top-10 of 16 per row -> global fidx ----
    if (tx < MTILE) {
        const int rl = tx;
        u64 bs[TOPK];
#pragma unroll
        for (int p = 0; p < TOPK; ++p) bs[p] = ~0ull;
#pragma unroll
        for (int v = 0; v < NCAND; ++v) {
            u64 key = EX[rl * NCAND + v];
            if (key < bs[TOPK - 1]) {
                bs[TOPK - 1] = key;
#pragma unroll
                for (int p = TOPK - 1; p > 0; --p)
                    if (bs[p] < bs[p - 1]) { u64 tm = bs[p]; bs[p] = bs[p - 1]; bs[p - 1] = tm; }
            }
        }
#pragma unroll
        for (int p = 0; p < TOPK; ++p)
            g_fidx[(size_t)(row0 + rl) * TOPK + p] = (int)(u32)(bs[p] & 0xffffffffu);
    }
}

// ---- dedicated gather: out[orow] = x[fidx[orow]], fully coalesced streaming ----
__global__ __launch_bounds__(256)
void gather_kernel(const float* __restrict__ x, float* __restrict__ out) {
    const float4* x4 = reinterpret_cast<const float4*>(x);
    float4* out4 = reinterpret_cast<float4*>(out);
    size_t i = (size_t)blockIdx.x * (256 * 20) + threadIdx.x;
#pragma unroll
    for (int it = 0; it < 20; ++it, i += 256) {
        size_t orow = i >> 5;
        int e = (int)(i & 31);
        int idx = g_fidx[orow];
        out4[i] = __ldg(&x4[(size_t)idx * 32 + e]);
    }
}

extern "C" void kernel_launch(void* const* d_in, const int* in_sizes, int n_in,
                              void* d_out, int out_size) {
    const float* x  = (const float*)d_in[0];
    const float* cc = (const float*)d_in[1];
    float* out = (float*)d_out;

    cudaFuncSetAttribute(kmeans_topk_kernel,
                         cudaFuncAttributeMaxDynamicSharedMemorySize, SMEM_TOTAL);
    c2_kernel<<<NC / 8, 256>>>(cc);
    kmeans_topk_kernel<<<NROWS / MTILE, NTHR, SMEM_TOTAL>>>(x, cc);
    // total out float4 = 32768*10*32 = 10485760 ; 2048 blocks * 256 thr * 20
    gather_kernel<<<2048, 256>>>(x, out);
}